// round 13
// baseline (speedup 1.0000x reference)
#include <cuda_runtime.h>

// ---------------- constants ----------------
#define NMAX   100000
#define CIN    64
#define CMID   32
#define KN     16
#define WNOUT  16
#define COUT   128

// ---------------- scratch ----------------
__device__ float g_feats32[NMAX * CMID];                 // 12.8 MB
__device__ float g_agg[(size_t)NMAX * 1024];             // 409.6 MB (row-major)
__device__ float g_x[(size_t)NMAX * 64];                 // 25.6 MB

__device__ __forceinline__ float lrelu(float v) { return v > 0.f ? v : 0.1f * v; }

#define FMA2(d, a, b, c) \
    asm("fma.rn.f32x2 %0, %1, %2, %3;" : "=l"(d) : "l"(a), "l"(b), "l"(c))

__device__ __forceinline__ unsigned long long pack2(float lo, float hi) {
    unsigned long long r;
    asm("mov.b64 %0, {%1, %2};" : "=l"(r) : "f"(lo), "f"(hi));
    return r;
}
__device__ __forceinline__ void unpack2(unsigned long long v, float& lo, float& hi) {
    asm("mov.b64 {%0, %1}, %2;" : "=f"(lo), "=f"(hi) : "l"(v));
}

// ============================================================================
// K1: feats32 = dense_feats @ u1_w + u1_b   (baseline-exact)
// ============================================================================
__global__ __launch_bounds__(128) void k1_unary1(
    const float* __restrict__ feats, const float* __restrict__ u1w,
    const float* __restrict__ u1b, int N)
{
    __shared__ float su[CIN * CMID];
    __shared__ float sf[4 * CIN];
    int t = threadIdx.x;
    int p0 = blockIdx.x * 4;
    for (int i = t; i < CIN * CMID; i += 128) su[i] = u1w[i];
#pragma unroll
    for (int q = 0; q < 2; q++) {
        int idx = q * 128 + t;
        int pl = idx >> 6, i = idx & 63;
        int p = p0 + pl;
        sf[idx] = (p < N) ? feats[p * CIN + i] : 0.f;
    }
    __syncthreads();
    int pl = t >> 5, c = t & 31;
    int p = p0 + pl;
    float acc = u1b[c];
#pragma unroll
    for (int i = 0; i < CIN; i++) acc += sf[pl * CIN + i] * su[i * CMID + c];
    if (p < N) g_feats32[p * CMID + c] = acc;
}

// ============================================================================
// K2: 4 points per 128-thread block — r12 + ONE change: s_ph stored SPLATTED
// in phase 3 so phase 4's inner loop is LDS.64 + FMA2 (no per-iter pack2).
// ============================================================================
__global__ __launch_bounds__(128) void k2_point(
    const float* __restrict__ xyz, const int* __restrict__ nei,
    const float* __restrict__ pw1, const float* __restrict__ pb1,
    const float* __restrict__ pw2, const float* __restrict__ pb2,
    const float* __restrict__ ww1, const float* __restrict__ wb1,
    const float* __restrict__ ww2, const float* __restrict__ wb2,
    const float* __restrict__ ww3, const float* __restrict__ wb3,
    float* __restrict__ loc_out, int N, int writeLoc)
{
    __shared__ float s_pw1[96], s_pb1[32];
    __shared__ __align__(16) float s_pw2[1024];
    __shared__ float s_pb2[32];
    __shared__ float s_ww1[24], s_wb1[8], s_ww2[64], s_wb2[8], s_ww3[128], s_wb3[16];
    __shared__ float s_loc[4][48];
    __shared__ __align__(16) float s_gf[4][512];    // [k][c]
    __shared__ __align__(16) float s_ph[4][1024];   // [h][2k] SPLATTED pairs
    __shared__ __align__(16) float s_pe[4][512];    // [k][c]
    __shared__ float s_wh1[4][128], s_wh2[4][128];
    __shared__ __align__(16) float s_w[4][256];     // [k][w]
    __shared__ int   s_nei[4][16];
    __shared__ float s_ctr[4][3];

    int p0 = blockIdx.x * 4;
    int t  = threadIdx.x;

    // ---- phase 1: weights + meta ----
    if (t < 96) s_pw1[t] = pw1[t];
    if (t < 32) { s_pb1[t] = pb1[t]; s_pb2[t] = pb2[t]; }
#pragma unroll
    for (int q = 0; q < 8; q++) s_pw2[q * 128 + t] = pw2[q * 128 + t];
    if (t < 24) s_ww1[t] = ww1[t];
    if (t >= 24 && t < 32) s_wb1[t - 24] = wb1[t - 24];
    if (t >= 32 && t < 96) s_ww2[t - 32] = ww2[t - 32];
    if (t >= 96 && t < 104) s_wb2[t - 96] = wb2[t - 96];
    s_ww3[t] = ww3[t];
    if (t >= 104 && t < 120) s_wb3[t - 104] = wb3[t - 104];
    if (t < 64) {
        int p = t >> 4, k = t & 15;
        s_nei[p][k] = (p0 + p < N) ? nei[(p0 + p) * KN + k] : 0;
    }
    if (t >= 64 && t < 76) {
        int i = t - 64, p = i / 3, d = i % 3;
        s_ctr[p][d] = (p0 + p < N) ? xyz[(p0 + p) * 3 + d] : 0.f;
    }
    __syncthreads();

    // ---- phase 2: localized + gather feats32 ----
#pragma unroll
    for (int q = 0; q < 2; q++) {
        int i = q * 128 + t;
        if (i < 192) {
            int p = i / 48, r = i - p * 48;
            int k = r / 3, d = r - k * 3;
            float v = xyz[s_nei[p][k] * 3 + d] - s_ctr[p][d];
            s_loc[p][r] = v;
            if (writeLoc && (p0 + p) < N) loc_out[(size_t)(p0 + p) * 48 + r] = v;
        }
    }
#pragma unroll
    for (int q = 0; q < 4; q++) {
        int idx = q * 128 + t;                 // 512 float4 slots
        int p = idx >> 7, rem = idx & 127;
        int k = rem >> 3, c4 = (rem & 7) * 4;
        *(float4*)&s_gf[p][k * 32 + c4] =
            *(const float4*)&g_feats32[(size_t)s_nei[p][k] * CMID + c4];
    }
    __syncthreads();

    // ---- phase 3: pe hidden (SPLATTED [h][2k]) + wn hidden1 ----
    {
        int k = t & 15, hb = t >> 4;
#pragma unroll
        for (int p = 0; p < 4; p++) {
            float l0 = s_loc[p][k * 3], l1 = s_loc[p][k * 3 + 1], l2 = s_loc[p][k * 3 + 2];
#pragma unroll
            for (int q = 0; q < 4; q++) {
                int h = hb + q * 8;
                float a = s_pb1[h] + l0 * s_pw1[h] + l1 * s_pw1[32 + h] + l2 * s_pw1[64 + h];
                float lr = lrelu(a);
                *(unsigned long long*)&s_ph[p][h * 32 + 2 * k] = pack2(lr, lr);
            }
        }
        int kk = t >> 3, hh = t & 7;
#pragma unroll
        for (int p = 0; p < 4; p++) {
            float m0 = s_loc[p][kk * 3], m1 = s_loc[p][kk * 3 + 1], m2 = s_loc[p][kk * 3 + 2];
            float a = s_wb1[hh] + m0 * s_ww1[hh] + m1 * s_ww1[8 + hh] + m2 * s_ww1[16 + hh];
            s_wh1[p][kk * 8 + hh] = lrelu(a);
        }
    }
    __syncthreads();

    // ---- phase 4: pe out (f32x2, wreg hoisted, splat ph reads) + wn hidden2 ----
    {
        int k0 = t >> 4;                       // 0..7
        int c0 = (t & 15) * 2;                 // identical for both q slots
        unsigned long long bias = pack2(s_pb2[c0], s_pb2[c0 + 1]);
        unsigned long long wreg[32];
#pragma unroll
        for (int h = 0; h < 32; h++)
            wreg[h] = *(const unsigned long long*)&s_pw2[h * 32 + c0];
#pragma unroll
        for (int q = 0; q < 2; q++) {
            int k = q * 8 + k0;                // q=0: 0..7, q=1: 8..15
#pragma unroll
            for (int p = 0; p < 4; p++) {
                unsigned long long a = bias;
#pragma unroll
                for (int h = 0; h < 32; h++) {
                    unsigned long long ph =
                        *(const unsigned long long*)&s_ph[p][h * 32 + 2 * k];
                    FMA2(a, ph, wreg[h], a);
                }
                float x0, x1; unpack2(a, x0, x1);
                s_pe[p][k * 32 + c0]     = lrelu(x0);
                s_pe[p][k * 32 + c0 + 1] = lrelu(x1);
            }
        }
        int kk = t >> 3, hh = t & 7;
#pragma unroll
        for (int p = 0; p < 4; p++) {
            float a = s_wb2[hh];
#pragma unroll
            for (int j = 0; j < 8; j++) a += s_wh1[p][kk * 8 + j] * s_ww2[j * 8 + hh];
            s_wh2[p][kk * 8 + hh] = a;
        }
    }
    __syncthreads();

    // ---- phase 5: wn final ----
#pragma unroll
    for (int q = 0; q < 2; q++) {
        int idx = q * 128 + t;
        int k = idx >> 4, wo = idx & 15;
#pragma unroll
        for (int p = 0; p < 4; p++) {
            float a = s_wb3[wo];
#pragma unroll
            for (int j = 0; j < 8; j++) a += s_wh2[p][k * 8 + j] * s_ww3[j * 16 + wo];
            s_w[p][k * 16 + wo] = lrelu(a);
        }
    }
    __syncthreads();

    // ---- phase 6: agg (f32x2) -> row-major g_agg ----
#pragma unroll
    for (int q = 0; q < 2; q++) {
        int slot = q * 128 + t;                // 256 slots = 4p * 64c
        int p = slot >> 6, c = slot & 63;
        const float* src = (c < 32) ? &s_gf[p][c] : &s_pe[p][c - 32];
        unsigned long long acc[8];
#pragma unroll
        for (int j = 0; j < 8; j++) acc[j] = 0ull;
#pragma unroll
        for (int k = 0; k < KN; k++) {
            float sv = src[k * 32];
            unsigned long long sp = pack2(sv, sv);
            ulonglong2 wa = *(const ulonglong2*)&s_w[p][k * 16];
            ulonglong2 wb = *(const ulonglong2*)&s_w[p][k * 16 + 4];
            ulonglong2 wc = *(const ulonglong2*)&s_w[p][k * 16 + 8];
            ulonglong2 wd = *(const ulonglong2*)&s_w[p][k * 16 + 12];
            FMA2(acc[0], sp, wa.x, acc[0]); FMA2(acc[1], sp, wa.y, acc[1]);
            FMA2(acc[2], sp, wb.x, acc[2]); FMA2(acc[3], sp, wb.y, acc[3]);
            FMA2(acc[4], sp, wc.x, acc[4]); FMA2(acc[5], sp, wc.y, acc[5]);
            FMA2(acc[6], sp, wd.x, acc[6]); FMA2(acc[7], sp, wd.y, acc[7]);
        }
        if (p0 + p < N) {
            float v[16];
#pragma unroll
            for (int j = 0; j < 8; j++) unpack2(acc[j], v[2 * j], v[2 * j + 1]);
            float* dst = &g_agg[(size_t)(p0 + p) * 1024 + c * 16];
            *(float4*)(dst)      = make_float4(v[0], v[1], v[2], v[3]);
            *(float4*)(dst + 4)  = make_float4(v[4], v[5], v[6], v[7]);
            *(float4*)(dst + 8)  = make_float4(v[8], v[9], v[10], v[11]);
            *(float4*)(dst + 12) = make_float4(v[12], v[13], v[14], v[15]);
        }
    }
}

// ============================================================================
// K3: x = leaky(agg @ lin_w + lin_b) — r12-exact (part of 854.5us baseline)
// ============================================================================
#define AS_STRIDE 544
__global__ __launch_bounds__(256, 2) void k3_lin(
    const float* __restrict__ lw, const float* __restrict__ lb, int N)
{
    __shared__ __align__(16) float As[16 * AS_STRIDE];   // splat [k][col]
    __shared__ __align__(16) float Ws[16 * 64];          // [k][swizzled j]
    int t  = threadIdx.x;
    int tb = blockIdx.x * 256;
    int ty = t >> 3, tx = t & 7;
    int r0 = ty * 8, j0 = tx * 8;

    size_t abase[4];
    int    lr[4], sg[4];
#pragma unroll
    for (int q = 0; q < 4; q++) {
        int slot = q * 256 + t;
        lr[q] = slot >> 2; sg[q] = slot & 3;
        int rowg = tb + lr[q]; if (rowg >= N) rowg = N - 1;
        abase[q] = (size_t)rowg * 1024 + sg[q] * 4;
    }
    int wk = t >> 4, wc4 = (t & 15) * 4;
    int wdst = wk * 64 + ((wc4 & 4) ? 32 : 0) + (wc4 >> 3) * 4;

    unsigned long long acc[32];
#pragma unroll
    for (int i = 0; i < 32; i++) acc[i] = 0ull;

    float4 pa[4];
#pragma unroll
    for (int q = 0; q < 4; q++) pa[q] = *(const float4*)&g_agg[abase[q]];
    float4 pw = *(const float4*)&lw[(size_t)wk * 64 + wc4];

    for (int kt = 0; kt < 64; kt++) {
        __syncthreads();
        {
#pragma unroll
            for (int q = 0; q < 4; q++) {
                int col = 2 * lr[q] + sg[q] * 8;
                float* a0 = &As[(sg[q] * 4) * AS_STRIDE + col];
                *(unsigned long long*)(a0 + 0 * AS_STRIDE) = pack2(pa[q].x, pa[q].x);
                *(unsigned long long*)(a0 + 1 * AS_STRIDE) = pack2(pa[q].y, pa[q].y);
                *(unsigned long long*)(a0 + 2 * AS_STRIDE) = pack2(pa[q].z, pa[q].z);
                *(unsigned long long*)(a0 + 3 * AS_STRIDE) = pack2(pa[q].w, pa[q].w);
            }
            *(float4*)&Ws[wdst] = pw;
        }
        __syncthreads();
        if (kt + 1 < 64) {
            int kb = (kt + 1) * 16;
#pragma unroll
            for (int q = 0; q < 4; q++) pa[q] = *(const float4*)&g_agg[abase[q] + kb];
            pw = *(const float4*)&lw[(size_t)(kb + wk) * 64 + wc4];
        }
#pragma unroll
        for (int k = 0; k < 16; k++) {
            int cb = k * AS_STRIDE + 2 * r0 + (k >> 2) * 8;
            ulonglong2 a01 = *(const ulonglong2*)&As[cb];
            ulonglong2 a23 = *(const ulonglong2*)&As[cb + 4];
            ulonglong2 a45 = *(const ulonglong2*)&As[cb + 8];
            ulonglong2 a67 = *(const ulonglong2*)&As[cb + 12];
            ulonglong2 w01 = *(const ulonglong2*)&Ws[k * 64 + tx * 4];
            ulonglong2 w23 = *(const ulonglong2*)&Ws[k * 64 + 32 + tx * 4];
            FMA2(acc[0],  a01.x, w01.x, acc[0]);  FMA2(acc[1],  a01.x, w01.y, acc[1]);
            FMA2(acc[2],  a01.x, w23.x, acc[2]);  FMA2(acc[3],  a01.x, w23.y, acc[3]);
            FMA2(acc[4],  a01.y, w01.x, acc[4]);  FMA2(acc[5],  a01.y, w01.y, acc[5]);
            FMA2(acc[6],  a01.y, w23.x, acc[6]);  FMA2(acc[7],  a01.y, w23.y, acc[7]);
            FMA2(acc[8],  a23.x, w01.x, acc[8]);  FMA2(acc[9],  a23.x, w01.y, acc[9]);
            FMA2(acc[10], a23.x, w23.x, acc[10]); FMA2(acc[11], a23.x, w23.y, acc[11]);
            FMA2(acc[12], a23.y, w01.x, acc[12]); FMA2(acc[13], a23.y, w01.y, acc[13]);
            FMA2(acc[14], a23.y, w23.x, acc[14]); FMA2(acc[15], a23.y, w23.y, acc[15]);
            FMA2(acc[16], a45.x, w01.x, acc[16]); FMA2(acc[17], a45.x, w01.y, acc[17]);
            FMA2(acc[18], a45.x, w23.x, acc[18]); FMA2(acc[19], a45.x, w23.y, acc[19]);
            FMA2(acc[20], a45.y, w01.x, acc[20]); FMA2(acc[21], a45.y, w01.y, acc[21]);
            FMA2(acc[22], a45.y, w23.x, acc[22]); FMA2(acc[23], a45.y, w23.y, acc[23]);
            FMA2(acc[24], a67.x, w01.x, acc[24]); FMA2(acc[25], a67.x, w01.y, acc[25]);
            FMA2(acc[26], a67.x, w23.x, acc[26]); FMA2(acc[27], a67.x, w23.y, acc[27]);
            FMA2(acc[28], a67.y, w01.x, acc[28]); FMA2(acc[29], a67.y, w01.y, acc[29]);
            FMA2(acc[30], a67.y, w23.x, acc[30]); FMA2(acc[31], a67.y, w23.y, acc[31]);
        }
    }
    float4 b0 = *(const float4*)&lb[j0];
    float4 b1 = *(const float4*)&lb[j0 + 4];
#pragma unroll
    for (int r = 0; r < 8; r++) {
        int row = tb + r0 + r;
        if (row < N) {
            float v[8];
            unpack2(acc[r * 4 + 0], v[0], v[1]);
            unpack2(acc[r * 4 + 1], v[2], v[3]);
            unpack2(acc[r * 4 + 2], v[4], v[5]);
            unpack2(acc[r * 4 + 3], v[6], v[7]);
            float* dst = &g_x[(size_t)row * 64 + j0];
            *(float4*)dst = make_float4(lrelu(v[0] + b0.x), lrelu(v[1] + b0.y),
                                        lrelu(v[2] + b0.z), lrelu(v[3] + b0.w));
            *(float4*)(dst + 4) = make_float4(lrelu(v[4] + b1.x), lrelu(v[5] + b1.y),
                                              lrelu(v[6] + b1.z), lrelu(v[7] + b1.w));
        }
    }
}

// ============================================================================
// K4: fused 128->128 GEMM — r12-exact (92.5us measured)
// ============================================================================
#define AS4_STRIDE 288
__global__ __launch_bounds__(256, 2) void k4_final(
    const float* __restrict__ feats, const float* __restrict__ u2w,
    const float* __restrict__ u2b, const float* __restrict__ scw,
    const float* __restrict__ scb, float* __restrict__ out, int N)
{
    __shared__ __align__(16) float As[16 * AS4_STRIDE];  // splat [k][col]
    __shared__ __align__(16) float Ws[16 * 128];         // [k][swizzled j]
    __shared__ float sb[128];
    int t  = threadIdx.x;
    int tb = blockIdx.x * 128;
    int ty = t >> 4, tx = t & 15;
    int r0 = ty * 8, j0 = tx * 8;

    int lr[2], sg[2], arow[2];
#pragma unroll
    for (int q = 0; q < 2; q++) {
        int slot = q * 256 + t;
        lr[q] = slot >> 2; sg[q] = slot & 3;
        int rowg = tb + lr[q]; if (rowg >= N) rowg = N - 1;
        arow[q] = rowg;
    }

    if (t < 128) sb[t] = u2b[t] + scb[t];

    unsigned long long acc[32];
#pragma unroll
    for (int i = 0; i < 32; i++) acc[i] = 0ull;

    float4 pa[2];
#pragma unroll
    for (int q = 0; q < 2; q++)
        pa[q] = *(const float4*)&g_x[(size_t)arow[q] * 64 + sg[q] * 4];
    int wk0 = t >> 5,        wc4 = (t & 31) * 4;
    int wk1 = 8 + (t >> 5);
    int woff = ((wc4 & 4) ? 64 : 0) + (wc4 >> 3) * 4;
    float4 pw0 = *(const float4*)&u2w[(size_t)wk0 * 128 + wc4];
    float4 pw1 = *(const float4*)&u2w[(size_t)wk1 * 128 + wc4];

    for (int ci = 0; ci < 8; ci++) {
        __syncthreads();
        {
#pragma unroll
            for (int q = 0; q < 2; q++) {
                int col = 2 * lr[q] + sg[q] * 8;
                float* a0 = &As[(sg[q] * 4) * AS4_STRIDE + col];
                *(unsigned long long*)(a0 + 0 * AS4_STRIDE) = pack2(pa[q].x, pa[q].x);
                *(unsigned long long*)(a0 + 1 * AS4_STRIDE) = pack2(pa[q].y, pa[q].y);
                *(unsigned long long*)(a0 + 2 * AS4_STRIDE) = pack2(pa[q].z, pa[q].z);
                *(unsigned long long*)(a0 + 3 * AS4_STRIDE) = pack2(pa[q].w, pa[q].w);
            }
            *(float4*)&Ws[wk0 * 128 + woff] = pw0;
            *(float4*)&Ws[wk1 * 128 + woff] = pw1;
        }
        __syncthreads();
        if (ci + 1 < 8) {
            int kb = (ci + 1) * 16;
#pragma unroll
            for (int q = 0; q < 2; q++) {
                const float* src = (kb < 64)
                    ? &g_x[(size_t)arow[q] * 64 + kb + sg[q] * 4]
                    : &feats[(size_t)arow[q] * 64 + (kb - 64) + sg[q] * 4];
                pa[q] = *(const float4*)src;
            }
            const float* w2 = (kb < 64) ? &u2w[(size_t)kb * 128] : &scw[(size_t)(kb - 64) * 128];
            pw0 = *(const float4*)&w2[(size_t)wk0 * 128 + wc4];
            pw1 = *(const float4*)&w2[(size_t)wk1 * 128 + wc4];
        }
#pragma unroll
        for (int k = 0; k < 16; k++) {
            int cb = k * AS4_STRIDE + 2 * r0 + (k >> 2) * 8;
            ulonglong2 a01 = *(const ulonglong2*)&As[cb];
            ulonglong2 a23 = *(const ulonglong2*)&As[cb + 4];
            ulonglong2 a45 = *(const ulonglong2*)&As[cb + 8];
            ulonglong2 a67 = *(const ulonglong2*)&As[cb + 12];
            ulonglong2 w01 = *(const ulonglong2*)&Ws[k * 128 + tx * 4];
            ulonglong2 w23 = *(const ulonglong2*)&Ws[k * 128 + 64 + tx * 4];
            FMA2(acc[0],  a01.x, w01.x, acc[0]);  FMA2(acc[1],  a01.x, w01.y, acc[1]);
            FMA2(acc[2],  a01.x, w23.x, acc[2]);  FMA2(acc[3],  a01.x, w23.y, acc[3]);
            FMA2(acc[4],  a01.y, w01.x, acc[4]);  FMA2(acc[5],  a01.y, w01.y, acc[5]);
            FMA2(acc[6],  a01.y, w23.x, acc[6]);  FMA2(acc[7],  a01.y, w23.y, acc[7]);
            FMA2(acc[8],  a23.x, w01.x, acc[8]);  FMA2(acc[9],  a23.x, w01.y, acc[9]);
            FMA2(acc[10], a23.x, w23.x, acc[10]); FMA2(acc[11], a23.x, w23.y, acc[11]);
            FMA2(acc[12], a23.y, w01.x, acc[12]); FMA2(acc[13], a23.y, w01.y, acc[13]);
            FMA2(acc[14], a23.y, w23.x, acc[14]); FMA2(acc[15], a23.y, w23.y, acc[15]);
            FMA2(acc[16], a45.x, w01.x, acc[16]); FMA2(acc[17], a45.x, w01.y, acc[17]);
            FMA2(acc[18], a45.x, w23.x, acc[18]); FMA2(acc[19], a45.x, w23.y, acc[19]);
            FMA2(acc[20], a45.y, w01.x, acc[20]); FMA2(acc[21], a45.y, w01.y, acc[21]);
            FMA2(acc[22], a45.y, w23.x, acc[22]); FMA2(acc[23], a45.y, w23.y, acc[23]);
            FMA2(acc[24], a67.x, w01.x, acc[24]); FMA2(acc[25], a67.x, w01.y, acc[25]);
            FMA2(acc[26], a67.x, w23.x, acc[26]); FMA2(acc[27], a67.x, w23.y, acc[27]);
            FMA2(acc[28], a67.y, w01.x, acc[28]); FMA2(acc[29], a67.y, w01.y, acc[29]);
            FMA2(acc[30], a67.y, w23.x, acc[30]); FMA2(acc[31], a67.y, w23.y, acc[31]);
        }
    }
    float4 b0 = *(const float4*)&sb[j0];
    float4 b1 = *(const float4*)&sb[j0 + 4];
#pragma unroll
    for (int r = 0; r < 8; r++) {
        int row = tb + r0 + r;
        if (row < N) {
            float v[8];
            unpack2(acc[r * 4 + 0], v[0], v[1]);
            unpack2(acc[r * 4 + 1], v[2], v[3]);
            unpack2(acc[r * 4 + 2], v[4], v[5]);
            unpack2(acc[r * 4 + 3], v[6], v[7]);
            float* dst = &out[(size_t)row * 128 + j0];
            *(float4*)dst = make_float4(lrelu(v[0] + b0.x), lrelu(v[1] + b0.y),
                                        lrelu(v[2] + b0.z), lrelu(v[3] + b0.w));
            *(float4*)(dst + 4) = make_float4(lrelu(v[4] + b1.x), lrelu(v[5] + b1.y),
                                              lrelu(v[6] + b1.z), lrelu(v[7] + b1.w));
        }
    }
}

// ============================================================================
// launch
// ============================================================================
extern "C" void kernel_launch(void* const* d_in, const int* in_sizes, int n_in,
                              void* d_out, int out_size)
{
    const float* xyz   = (const float*)d_in[0];
    const float* feats = (const float*)d_in[1];
    const int*   nei   = (const int*)  d_in[2];
    const float* pw1 = (const float*)d_in[3];
    const float* pb1 = (const float*)d_in[4];
    const float* pw2 = (const float*)d_in[5];
    const float* pb2 = (const float*)d_in[6];
    const float* u1w = (const float*)d_in[7];
    const float* u1b = (const float*)d_in[8];
    const float* ww1 = (const float*)d_in[9];
    const float* wb1 = (const float*)d_in[10];
    const float* ww2 = (const float*)d_in[11];
    const float* wb2 = (const float*)d_in[12];
    const float* ww3 = (const float*)d_in[13];
    const float* wb3 = (const float*)d_in[14];
    const float* lw  = (const float*)d_in[15];
    const float* lb  = (const float*)d_in[16];
    const float* u2w = (const float*)d_in[17];
    const float* u2b = (const float*)d_in[18];
    const float* scw = (const float*)d_in[19];
    const float* scb = (const float*)d_in[20];

    int N = in_sizes[0] / 3;
    if (N > NMAX) N = NMAX;

    float* out = (float*)d_out;
    long long need = (long long)N * 128 + (long long)N * 48;
    int writeLoc = ((long long)out_size >= need) ? 1 : 0;
    float* loc_out = out + (size_t)N * 128;

    k1_unary1<<<(N + 3) / 4, 128>>>(feats, u1w, u1b, N);
    k2_point<<<(N + 3) / 4, 128>>>(xyz, nei, pw1, pb1, pw2, pb2,
                                   ww1, wb1, ww2, wb2, ww3, wb3,
                                   loc_out, N, writeLoc);
    k3_lin<<<(N + 255) / 256, 256>>>(lw, lb, N);
    k4_final<<<(N + 127) / 128, 256>>>(feats, u2w, u2b, scw, scb, out, N);
}

// round 15
// speedup vs baseline: 1.1057x; 1.1057x over previous
#include <cuda_runtime.h>

// ---------------- constants ----------------
#define NMAX   100000
#define CIN    64
#define CMID   32
#define KN     16
#define WNOUT  16
#define COUT   128

// ---------------- scratch ----------------
__device__ float g_feats32[NMAX * CMID];                 // 12.8 MB
__device__ float g_agg[(size_t)NMAX * 1024];             // 409.6 MB (row-major)
__device__ float g_x[(size_t)NMAX * 64];                 // 25.6 MB

__device__ __forceinline__ float lrelu(float v) { return v > 0.f ? v : 0.1f * v; }

#define FMA2(d, a, b, c) \
    asm("fma.rn.f32x2 %0, %1, %2, %3;" : "=l"(d) : "l"(a), "l"(b), "l"(c))

__device__ __forceinline__ unsigned long long pack2(float lo, float hi) {
    unsigned long long r;
    asm("mov.b64 %0, {%1, %2};" : "=l"(r) : "f"(lo), "f"(hi));
    return r;
}
__device__ __forceinline__ void unpack2(unsigned long long v, float& lo, float& hi) {
    asm("mov.b64 {%0, %1}, %2;" : "=f"(lo), "=f"(hi) : "l"(v));
}

// bf16 helpers (baseline ISA)
__device__ __forceinline__ unsigned cvtbf2(float lo, float hi) {
    unsigned r;   // r = {lo16: bf16(lo), hi16: bf16(hi)}
    asm("cvt.rn.bf16x2.f32 %0, %1, %2;" : "=r"(r) : "f"(hi), "f"(lo));
    return r;
}
__device__ __forceinline__ unsigned short f2bf(float f) {
    unsigned u = __float_as_uint(f);
    u = u + 0x7FFFu + ((u >> 16) & 1u);
    return (unsigned short)(u >> 16);
}
__device__ __forceinline__ float bf2f(unsigned short h) {
    return __uint_as_float(((unsigned)h) << 16);
}
// warp-level bf16 MMA, fp32 accumulate (sm_80+ baseline ISA)
__device__ __forceinline__ void mma_bf16(float d[4], const unsigned a[4], const unsigned b[2]) {
    asm volatile(
        "mma.sync.aligned.m16n8k16.row.col.f32.bf16.bf16.f32 "
        "{%0,%1,%2,%3}, {%4,%5,%6,%7}, {%8,%9}, {%0,%1,%2,%3};"
        : "+f"(d[0]), "+f"(d[1]), "+f"(d[2]), "+f"(d[3])
        : "r"(a[0]), "r"(a[1]), "r"(a[2]), "r"(a[3]), "r"(b[0]), "r"(b[1]));
}

// ============================================================================
// K1: feats32 = dense_feats @ u1_w + u1_b   (baseline-exact)
// ============================================================================
__global__ __launch_bounds__(128) void k1_unary1(
    const float* __restrict__ feats, const float* __restrict__ u1w,
    const float* __restrict__ u1b, int N)
{
    __shared__ float su[CIN * CMID];
    __shared__ float sf[4 * CIN];
    int t = threadIdx.x;
    int p0 = blockIdx.x * 4;
    for (int i = t; i < CIN * CMID; i += 128) su[i] = u1w[i];
#pragma unroll
    for (int q = 0; q < 2; q++) {
        int idx = q * 128 + t;
        int pl = idx >> 6, i = idx & 63;
        int p = p0 + pl;
        sf[idx] = (p < N) ? feats[p * CIN + i] : 0.f;
    }
    __syncthreads();
    int pl = t >> 5, c = t & 31;
    int p = p0 + pl;
    float acc = u1b[c];
#pragma unroll
    for (int i = 0; i < CIN; i++) acc += sf[pl * CIN + i] * su[i * CMID + c];
    if (p < N) g_feats32[p * CMID + c] = acc;
}

// ============================================================================
// K2: 4 points per 128-thread block — r12-exact (854.5us baseline version)
// ============================================================================
__global__ __launch_bounds__(128) void k2_point(
    const float* __restrict__ xyz, const int* __restrict__ nei,
    const float* __restrict__ pw1, const float* __restrict__ pb1,
    const float* __restrict__ pw2, const float* __restrict__ pb2,
    const float* __restrict__ ww1, const float* __restrict__ wb1,
    const float* __restrict__ ww2, const float* __restrict__ wb2,
    const float* __restrict__ ww3, const float* __restrict__ wb3,
    float* __restrict__ loc_out, int N, int writeLoc)
{
    __shared__ float s_pw1[96], s_pb1[32];
    __shared__ __align__(16) float s_pw2[1024];
    __shared__ float s_pb2[32];
    __shared__ float s_ww1[24], s_wb1[8], s_ww2[64], s_wb2[8], s_ww3[128], s_wb3[16];
    __shared__ float s_loc[4][48];
    __shared__ __align__(16) float s_gf[4][512];
    __shared__ float s_ph[4][512];                  // [h][k] transposed
    __shared__ __align__(16) float s_pe[4][512];
    __shared__ float s_wh1[4][128], s_wh2[4][128];
    __shared__ __align__(16) float s_w[4][256];
    __shared__ int   s_nei[4][16];
    __shared__ float s_ctr[4][3];

    int p0 = blockIdx.x * 4;
    int t  = threadIdx.x;

    if (t < 96) s_pw1[t] = pw1[t];
    if (t < 32) { s_pb1[t] = pb1[t]; s_pb2[t] = pb2[t]; }
#pragma unroll
    for (int q = 0; q < 8; q++) s_pw2[q * 128 + t] = pw2[q * 128 + t];
    if (t < 24) s_ww1[t] = ww1[t];
    if (t >= 24 && t < 32) s_wb1[t - 24] = wb1[t - 24];
    if (t >= 32 && t < 96) s_ww2[t - 32] = ww2[t - 32];
    if (t >= 96 && t < 104) s_wb2[t - 96] = wb2[t - 96];
    s_ww3[t] = ww3[t];
    if (t >= 104 && t < 120) s_wb3[t - 104] = wb3[t - 104];
    if (t < 64) {
        int p = t >> 4, k = t & 15;
        s_nei[p][k] = (p0 + p < N) ? nei[(p0 + p) * KN + k] : 0;
    }
    if (t >= 64 && t < 76) {
        int i = t - 64, p = i / 3, d = i % 3;
        s_ctr[p][d] = (p0 + p < N) ? xyz[(p0 + p) * 3 + d] : 0.f;
    }
    __syncthreads();

#pragma unroll
    for (int q = 0; q < 2; q++) {
        int i = q * 128 + t;
        if (i < 192) {
            int p = i / 48, r = i - p * 48;
            int k = r / 3, d = r - k * 3;
            float v = xyz[s_nei[p][k] * 3 + d] - s_ctr[p][d];
            s_loc[p][r] = v;
            if (writeLoc && (p0 + p) < N) loc_out[(size_t)(p0 + p) * 48 + r] = v;
        }
    }
#pragma unroll
    for (int q = 0; q < 4; q++) {
        int idx = q * 128 + t;
        int p = idx >> 7, rem = idx & 127;
        int k = rem >> 3, c4 = (rem & 7) * 4;
        *(float4*)&s_gf[p][k * 32 + c4] =
            *(const float4*)&g_feats32[(size_t)s_nei[p][k] * CMID + c4];
    }
    __syncthreads();

    {
        int k = t & 15, hb = t >> 4;
#pragma unroll
        for (int p = 0; p < 4; p++) {
            float l0 = s_loc[p][k * 3], l1 = s_loc[p][k * 3 + 1], l2 = s_loc[p][k * 3 + 2];
#pragma unroll
            for (int q = 0; q < 4; q++) {
                int h = hb + q * 8;
                float a = s_pb1[h] + l0 * s_pw1[h] + l1 * s_pw1[32 + h] + l2 * s_pw1[64 + h];
                s_ph[p][h * 16 + k] = lrelu(a);
            }
        }
        int kk = t >> 3, hh = t & 7;
#pragma unroll
        for (int p = 0; p < 4; p++) {
            float m0 = s_loc[p][kk * 3], m1 = s_loc[p][kk * 3 + 1], m2 = s_loc[p][kk * 3 + 2];
            float a = s_wb1[hh] + m0 * s_ww1[hh] + m1 * s_ww1[8 + hh] + m2 * s_ww1[16 + hh];
            s_wh1[p][kk * 8 + hh] = lrelu(a);
        }
    }
    __syncthreads();

    {
        int k0 = t >> 4;
        int c0 = (t & 15) * 2;
        unsigned long long bias = pack2(s_pb2[c0], s_pb2[c0 + 1]);
        unsigned long long wreg[32];
#pragma unroll
        for (int h = 0; h < 32; h++)
            wreg[h] = *(const unsigned long long*)&s_pw2[h * 32 + c0];
#pragma unroll
        for (int q = 0; q < 2; q++) {
            int k = q * 8 + k0;
#pragma unroll
            for (int p = 0; p < 4; p++) {
                unsigned long long a = bias;
#pragma unroll
                for (int h = 0; h < 32; h++) {
                    float pv = s_ph[p][h * 16 + k];
                    unsigned long long ps = pack2(pv, pv);
                    FMA2(a, ps, wreg[h], a);
                }
                float x0, x1; unpack2(a, x0, x1);
                s_pe[p][k * 32 + c0]     = lrelu(x0);
                s_pe[p][k * 32 + c0 + 1] = lrelu(x1);
            }
        }
        int kk = t >> 3, hh = t & 7;
#pragma unroll
        for (int p = 0; p < 4; p++) {
            float a = s_wb2[hh];
#pragma unroll
            for (int j = 0; j < 8; j++) a += s_wh1[p][kk * 8 + j] * s_ww2[j * 8 + hh];
            s_wh2[p][kk * 8 + hh] = a;
        }
    }
    __syncthreads();

#pragma unroll
    for (int q = 0; q < 2; q++) {
        int idx = q * 128 + t;
        int k = idx >> 4, wo = idx & 15;
#pragma unroll
        for (int p = 0; p < 4; p++) {
            float a = s_wb3[wo];
#pragma unroll
            for (int j = 0; j < 8; j++) a += s_wh2[p][k * 8 + j] * s_ww3[j * 16 + wo];
            s_w[p][k * 16 + wo] = lrelu(a);
        }
    }
    __syncthreads();

#pragma unroll
    for (int q = 0; q < 2; q++) {
        int slot = q * 128 + t;
        int p = slot >> 6, c = slot & 63;
        const float* src = (c < 32) ? &s_gf[p][c] : &s_pe[p][c - 32];
        unsigned long long acc[8];
#pragma unroll
        for (int j = 0; j < 8; j++) acc[j] = 0ull;
#pragma unroll
        for (int k = 0; k < KN; k++) {
            float sv = src[k * 32];
            unsigned long long sp = pack2(sv, sv);
            ulonglong2 wa = *(const ulonglong2*)&s_w[p][k * 16];
            ulonglong2 wb = *(const ulonglong2*)&s_w[p][k * 16 + 4];
            ulonglong2 wc = *(const ulonglong2*)&s_w[p][k * 16 + 8];
            ulonglong2 wd = *(const ulonglong2*)&s_w[p][k * 16 + 12];
            FMA2(acc[0], sp, wa.x, acc[0]); FMA2(acc[1], sp, wa.y, acc[1]);
            FMA2(acc[2], sp, wb.x, acc[2]); FMA2(acc[3], sp, wb.y, acc[3]);
            FMA2(acc[4], sp, wc.x, acc[4]); FMA2(acc[5], sp, wc.y, acc[5]);
            FMA2(acc[6], sp, wd.x, acc[6]); FMA2(acc[7], sp, wd.y, acc[7]);
        }
        if (p0 + p < N) {
            float v[16];
#pragma unroll
            for (int j = 0; j < 8; j++) unpack2(acc[j], v[2 * j], v[2 * j + 1]);
            float* dst = &g_agg[(size_t)(p0 + p) * 1024 + c * 16];
            *(float4*)(dst)      = make_float4(v[0], v[1], v[2], v[3]);
            *(float4*)(dst + 4)  = make_float4(v[4], v[5], v[6], v[7]);
            *(float4*)(dst + 8)  = make_float4(v[8], v[9], v[10], v[11]);
            *(float4*)(dst + 12) = make_float4(v[12], v[13], v[14], v[15]);
        }
    }
}

// ============================================================================
// K3 (NEW): warp-level bf16-split MMA.  x = leaky(agg @ lin_w + lin_b)
// 256 thr / 128 rows per CTA; warp = 16-row m-tile x N=64 (8 n-subtiles).
// D += Ah*Bh + Ah*Bl + Al*Bh via mma.sync m16n8k16 bf16 (fp32 accum).
// A/B split to hi/lo bf16 in smem; rows padded to 40 bf16 (conflict-free).
// ============================================================================
#define MST 40   // bf16 row stride
__global__ __launch_bounds__(256, 2) void k3_mma(
    const float* __restrict__ lw, const float* __restrict__ lb, int N)
{
    __shared__ __align__(16) unsigned short sAh[128 * MST];
    __shared__ __align__(16) unsigned short sAl[128 * MST];
    __shared__ __align__(16) unsigned short sBh[64 * MST];
    __shared__ __align__(16) unsigned short sBl[64 * MST];

    int t = threadIdx.x;
    int lane = t & 31, warp = t >> 5;
    int g = lane >> 2, tig = lane & 3;
    int mb = warp * 16;
    int tb = blockIdx.x * 128;

    float acc[8][4];
#pragma unroll
    for (int ns = 0; ns < 8; ns++)
#pragma unroll
        for (int i = 0; i < 4; i++) acc[ns][i] = 0.f;

    for (int ch = 0; ch < 32; ch++) {
        int kb = ch * 32;
        // ---- A: 128 rows x 32 k fp32 -> hi/lo bf16 (coalesced 8-line LDGs) ----
#pragma unroll
        for (int q = 0; q < 4; q++) {
            int slot = q * 256 + t;
            int row = slot >> 3, seg = slot & 7;       // seg: k = seg*4
            int grow = tb + row; if (grow >= N) grow = N - 1;
            float4 v = *(const float4*)&g_agg[(size_t)grow * 1024 + kb + seg * 4];
            unsigned hp0 = cvtbf2(v.x, v.y);
            unsigned hp1 = cvtbf2(v.z, v.w);
            float rx = v.x - __uint_as_float(hp0 << 16);
            float ry = v.y - __uint_as_float(hp0 & 0xFFFF0000u);
            float rz = v.z - __uint_as_float(hp1 << 16);
            float rw = v.w - __uint_as_float(hp1 & 0xFFFF0000u);
            unsigned lp0 = cvtbf2(rx, ry);
            unsigned lp1 = cvtbf2(rz, rw);
            uint2* dh = (uint2*)&sAh[row * MST + seg * 4];
            uint2* dl = (uint2*)&sAl[row * MST + seg * 4];
            *dh = make_uint2(hp0, hp1);
            *dl = make_uint2(lp0, lp1);
        }
        // ---- B: lw[kb..kb+31][0..63] -> [n][k] hi/lo bf16 (transposed) ----
#pragma unroll
        for (int q = 0; q < 2; q++) {
            int slot = q * 256 + t;
            int k = slot >> 4, n4 = (slot & 15) * 4;
            float4 v = *(const float4*)&lw[(size_t)(kb + k) * 64 + n4];
            float vv[4] = {v.x, v.y, v.z, v.w};
#pragma unroll
            for (int i = 0; i < 4; i++) {
                unsigned short h = f2bf(vv[i]);
                unsigned short l = f2bf(vv[i] - bf2f(h));
                sBh[(n4 + i) * MST + k] = h;
                sBl[(n4 + i) * MST + k] = l;
            }
        }
        __syncthreads();
        // ---- compute: 2 k-steps of 16, 8 n-subtiles, 3 products each ----
#pragma unroll
        for (int ks = 0; ks < 2; ks++) {
            int ko = ks * 16 + tig * 2;
            unsigned ah[4], al[4];
            ah[0] = *(const unsigned*)&sAh[(mb + g) * MST + ko];
            ah[1] = *(const unsigned*)&sAh[(mb + g + 8) * MST + ko];
            ah[2] = *(const unsigned*)&sAh[(mb + g) * MST + ko + 8];
            ah[3] = *(const unsigned*)&sAh[(mb + g + 8) * MST + ko + 8];
            al[0] = *(const unsigned*)&sAl[(mb + g) * MST + ko];
            al[1] = *(const unsigned*)&sAl[(mb + g + 8) * MST + ko];
            al[2] = *(const unsigned*)&sAl[(mb + g) * MST + ko + 8];
            al[3] = *(const unsigned*)&sAl[(mb + g + 8) * MST + ko + 8];
#pragma unroll
            for (int ns = 0; ns < 8; ns++) {
                int n = ns * 8 + g;
                unsigned bh[2], bl[2];
                bh[0] = *(const unsigned*)&sBh[n * MST + ko];
                bh[1] = *(const unsigned*)&sBh[n * MST + ko + 8];
                bl[0] = *(const unsigned*)&sBl[n * MST + ko];
                bl[1] = *(const unsigned*)&sBl[n * MST + ko + 8];
                mma_bf16(acc[ns], ah, bh);
                mma_bf16(acc[ns], ah, bl);
                mma_bf16(acc[ns], al, bh);
            }
        }
        __syncthreads();
    }

    // ---- epilogue: bias + leaky, write g_x ----
    int ra = tb + mb + g;
    int rb = ra + 8;
#pragma unroll
    for (int ns = 0; ns < 8; ns++) {
        int c0 = ns * 8 + tig * 2;
        float b0 = lb[c0], b1 = lb[c0 + 1];
        if (ra < N) {
            float2* d = (float2*)&g_x[(size_t)ra * 64 + c0];
            *d = make_float2(lrelu(acc[ns][0] + b0), lrelu(acc[ns][1] + b1));
        }
        if (rb < N) {
            float2* d = (float2*)&g_x[(size_t)rb * 64 + c0];
            *d = make_float2(lrelu(acc[ns][2] + b0), lrelu(acc[ns][3] + b1));
        }
    }
}

// ============================================================================
// K4: fused 128->128 GEMM — r12-exact (92us measured)
// ============================================================================
#define AS4_STRIDE 288
__global__ __launch_bounds__(256, 2) void k4_final(
    const float* __restrict__ feats, const float* __restrict__ u2w,
    const float* __restrict__ u2b, const float* __restrict__ scw,
    const float* __restrict__ scb, float* __restrict__ out, int N)
{
    __shared__ __align__(16) float As[16 * AS4_STRIDE];
    __shared__ __align__(16) float Ws[16 * 128];
    __shared__ float sb[128];
    int t  = threadIdx.x;
    int tb = blockIdx.x * 128;
    int ty = t >> 4, tx = t & 15;
    int r0 = ty * 8, j0 = tx * 8;

    int lr[2], sg[2], arow[2];
#pragma unroll
    for (int q = 0; q < 2; q++) {
        int slot = q * 256 + t;
        lr[q] = slot >> 2; sg[q] = slot & 3;
        int rowg = tb + lr[q]; if (rowg >= N) rowg = N - 1;
        arow[q] = rowg;
    }

    if (t < 128) sb[t] = u2b[t] + scb[t];

    unsigned long long acc[32];
#pragma unroll
    for (int i = 0; i < 32; i++) acc[i] = 0ull;

    float4 pa[2];
#pragma unroll
    for (int q = 0; q < 2; q++)
        pa[q] = *(const float4*)&g_x[(size_t)arow[q] * 64 + sg[q] * 4];
    int wk0 = t >> 5,        wc4 = (t & 31) * 4;
    int wk1 = 8 + (t >> 5);
    int woff = ((wc4 & 4) ? 64 : 0) + (wc4 >> 3) * 4;
    float4 pw0 = *(const float4*)&u2w[(size_t)wk0 * 128 + wc4];
    float4 pw1 = *(const float4*)&u2w[(size_t)wk1 * 128 + wc4];

    for (int ci = 0; ci < 8; ci++) {
        __syncthreads();
        {
#pragma unroll
            for (int q = 0; q < 2; q++) {
                int col = 2 * lr[q] + sg[q] * 8;
                float* a0 = &As[(sg[q] * 4) * AS4_STRIDE + col];
                *(unsigned long long*)(a0 + 0 * AS4_STRIDE) = pack2(pa[q].x, pa[q].x);
                *(unsigned long long*)(a0 + 1 * AS4_STRIDE) = pack2(pa[q].y, pa[q].y);
                *(unsigned long long*)(a0 + 2 * AS4_STRIDE) = pack2(pa[q].z, pa[q].z);
                *(unsigned long long*)(a0 + 3 * AS4_STRIDE) = pack2(pa[q].w, pa[q].w);
            }
            *(float4*)&Ws[wk0 * 128 + woff] = pw0;
            *(float4*)&Ws[wk1 * 128 + woff] = pw1;
        }
        __syncthreads();
        if (ci + 1 < 8) {
            int kb = (ci + 1) * 16;
#pragma unroll
            for (int q = 0; q < 2; q++) {
                const float* src = (kb < 64)
                    ? &g_x[(size_t)arow[q] * 64 + kb + sg[q] * 4]
                    : &feats[(size_t)arow[q] * 64 + (kb - 64) + sg[q] * 4];
                pa[q] = *(const float4*)src;
            }
            const float* w2 = (kb < 64) ? &u2w[(size_t)kb * 128] : &scw[(size_t)(kb - 64) * 128];
            pw0 = *(const float4*)&w2[(size_t)wk0 * 128 + wc4];
            pw1 = *(const float4*)&w2[(size_t)wk1 * 128 + wc4];
        }
#pragma unroll
        for (int k = 0; k < 16; k++) {
            int cb = k * AS4_STRIDE + 2 * r0 + (k >> 2) * 8;
            ulonglong2 a01 = *(const ulonglong2*)&As[cb];
            ulonglong2 a23 = *(const ulonglong2*)&As[cb + 4];
            ulonglong2 a45 = *(const ulonglong2*)&As[cb + 8];
            ulonglong2 a67 = *(const ulonglong2*)&As[cb + 12];
            ulonglong2 w01 = *(const ulonglong2*)&Ws[k * 128 + tx * 4];
            ulonglong2 w23 = *(const ulonglong2*)&Ws[k * 128 + 64 + tx * 4];
            FMA2(acc[0],  a01.x, w01.x, acc[0]);  FMA2(acc[1],  a01.x, w01.y, acc[1]);
            FMA2(acc[2],  a01.x, w23.x, acc[2]);  FMA2(acc[3],  a01.x, w23.y, acc[3]);
            FMA2(acc[4],  a01.y, w01.x, acc[4]);  FMA2(acc[5],  a01.y, w01.y, acc[5]);
            FMA2(acc[6],  a01.y, w23.x, acc[6]);  FMA2(acc[7],  a01.y, w23.y, acc[7]);
            FMA2(acc[8],  a23.x, w01.x, acc[8]);  FMA2(acc[9],  a23.x, w01.y, acc[9]);
            FMA2(acc[10], a23.x, w23.x, acc[10]); FMA2(acc[11], a23.x, w23.y, acc[11]);
            FMA2(acc[12], a23.y, w01.x, acc[12]); FMA2(acc[13], a23.y, w01.y, acc[13]);
            FMA2(acc[14], a23.y, w23.x, acc[14]); FMA2(acc[15], a23.y, w23.y, acc[15]);
            FMA2(acc[16], a45.x, w01.x, acc[16]); FMA2(acc[17], a45.x, w01.y, acc[17]);
            FMA2(acc[18], a45.x, w23.x, acc[18]); FMA2(acc[19], a45.x, w23.y, acc[19]);
            FMA2(acc[20], a45.y, w01.x, acc[20]); FMA2(acc[21], a45.y, w01.y, acc[21]);
            FMA2(acc[22], a45.y, w23.x, acc[22]); FMA2(acc[23], a45.y, w23.y, acc[23]);
            FMA2(acc[24], a67.x, w01.x, acc[24]); FMA2(acc[25], a67.x, w01.y, acc[25]);
            FMA2(acc[26], a67.x, w23.x, acc[26]); FMA2(acc[27], a67.x, w23.y, acc[27]);
            FMA2(acc[28], a67.y, w01.x, acc[28]); FMA2(acc[29], a67.y, w01.y, acc[29]);
            FMA2(acc[30], a67.y, w23.x, acc[30]); FMA2(acc[31], a67.y, w23.y, acc[31]);
        }
    }
    float4 b0 = *(const float4*)&sb[j0];
    float4 b1 = *(const float4*)&sb[j0 + 4];
#pragma unroll
    for (int r = 0; r < 8; r++) {
        int row = tb + r0 + r;
        if (row < N) {
            float v[8];
            unpack2(acc[r * 4 + 0], v[0], v[1]);
            unpack2(acc[r * 4 + 1], v[2], v[3]);
            unpack2(acc[r * 4 + 2], v[4], v[5]);
            unpack2(acc[r * 4 + 3], v[6], v[7]);
            float* dst = &out[(size_t)row * 128 + j0];
            *(float4*)dst = make_float4(lrelu(v[0] + b0.x), lrelu(v[1] + b0.y),
                                        lrelu(v[2] + b0.z), lrelu(v[3] + b0.w));
            *(float4*)(dst + 4) = make_float4(lrelu(v[4] + b1.x), lrelu(v[5] + b1.y),
                                              lrelu(v[6] + b1.z), lrelu(v[7] + b1.w));
        }
    }
}

// ============================================================================
// launch
// ============================================================================
extern "C" void kernel_launch(void* const* d_in, const int* in_sizes, int n_in,
                              void* d_out, int out_size)
{
    const float* xyz   = (const float*)d_in[0];
    const float* feats = (const float*)d_in[1];
    const int*   nei   = (const int*)  d_in[2];
    const float* pw1 = (const float*)d_in[3];
    const float* pb1 = (const float*)d_in[4];
    const float* pw2 = (const float*)d_in[5];
    const float* pb2 = (const float*)d_in[6];
    const float* u1w = (const float*)d_in[7];
    const float* u1b = (const float*)d_in[8];
    const float* ww1 = (const float*)d_in[9];
    const float* wb1 = (const float*)d_in[10];
    const float* ww2 = (const float*)d_in[11];
    const float* wb2 = (const float*)d_in[12];
    const float* ww3 = (const float*)d_in[13];
    const float* wb3 = (const float*)d_in[14];
    const float* lw  = (const float*)d_in[15];
    const float* lb  = (const float*)d_in[16];
    const float* u2w = (const float*)d_in[17];
    const float* u2b = (const float*)d_in[18];
    const float* scw = (const float*)d_in[19];
    const float* scb = (const float*)d_in[20];

    int N = in_sizes[0] / 3;
    if (N > NMAX) N = NMAX;

    float* out = (float*)d_out;
    long long need = (long long)N * 128 + (long long)N * 48;
    int writeLoc = ((long long)out_size >= need) ? 1 : 0;
    float* loc_out = out + (size_t)N * 128;

    k1_unary1<<<(N + 3) / 4, 128>>>(feats, u1w, u1b, N);
    k2_point<<<(N + 3) / 4, 128>>>(xyz, nei, pw1, pb1, pw2, pb2,
                                   ww1, wb1, ww2, wb2, ww3, wb3,
                                   loc_out, N, writeLoc);
    k3_mma<<<(N + 127) / 128, 256>>>(lw, lb, N);
    k4_final<<<(N + 127) / 128, 256>>>(feats, u2w, u2b, scw, scb, out, N);
}

// round 16
// speedup vs baseline: 1.1402x; 1.0312x over previous
#include <cuda_runtime.h>

// ---------------- constants ----------------
#define NMAX   100000
#define CIN    64
#define CMID   32
#define KN     16
#define WNOUT  16
#define COUT   128

// ---------------- scratch ----------------
__device__ float g_feats32[NMAX * CMID];                 // 12.8 MB
__device__ float g_agg[(size_t)NMAX * 1024];             // 409.6 MB (row-major)
__device__ float g_x[(size_t)NMAX * 64];                 // 25.6 MB

__device__ __forceinline__ float lrelu(float v) { return v > 0.f ? v : 0.1f * v; }

#define FMA2(d, a, b, c) \
    asm("fma.rn.f32x2 %0, %1, %2, %3;" : "=l"(d) : "l"(a), "l"(b), "l"(c))

__device__ __forceinline__ unsigned long long pack2(float lo, float hi) {
    unsigned long long r;
    asm("mov.b64 %0, {%1, %2};" : "=l"(r) : "f"(lo), "f"(hi));
    return r;
}
__device__ __forceinline__ void unpack2(unsigned long long v, float& lo, float& hi) {
    asm("mov.b64 {%0, %1}, %2;" : "=f"(lo), "=f"(hi) : "l"(v));
}

// bf16 helpers (baseline ISA)
__device__ __forceinline__ unsigned cvtbf2(float lo, float hi) {
    unsigned r;   // r = {lo16: bf16(lo), hi16: bf16(hi)}
    asm("cvt.rn.bf16x2.f32 %0, %1, %2;" : "=r"(r) : "f"(hi), "f"(lo));
    return r;
}
__device__ __forceinline__ unsigned short f2bf(float f) {
    unsigned u = __float_as_uint(f);
    u = u + 0x7FFFu + ((u >> 16) & 1u);
    return (unsigned short)(u >> 16);
}
__device__ __forceinline__ float bf2f(unsigned short h) {
    return __uint_as_float(((unsigned)h) << 16);
}
// warp-level bf16 MMA, fp32 accumulate (sm_80+ baseline ISA)
__device__ __forceinline__ void mma_bf16(float d[4], const unsigned a[4], const unsigned b[2]) {
    asm volatile(
        "mma.sync.aligned.m16n8k16.row.col.f32.bf16.bf16.f32 "
        "{%0,%1,%2,%3}, {%4,%5,%6,%7}, {%8,%9}, {%0,%1,%2,%3};"
        : "+f"(d[0]), "+f"(d[1]), "+f"(d[2]), "+f"(d[3])
        : "r"(a[0]), "r"(a[1]), "r"(a[2]), "r"(a[3]), "r"(b[0]), "r"(b[1]));
}

// ============================================================================
// K1: feats32 = dense_feats @ u1_w + u1_b   (baseline-exact)
// ============================================================================
__global__ __launch_bounds__(128) void k1_unary1(
    const float* __restrict__ feats, const float* __restrict__ u1w,
    const float* __restrict__ u1b, int N)
{
    __shared__ float su[CIN * CMID];
    __shared__ float sf[4 * CIN];
    int t = threadIdx.x;
    int p0 = blockIdx.x * 4;
    for (int i = t; i < CIN * CMID; i += 128) su[i] = u1w[i];
#pragma unroll
    for (int q = 0; q < 2; q++) {
        int idx = q * 128 + t;
        int pl = idx >> 6, i = idx & 63;
        int p = p0 + pl;
        sf[idx] = (p < N) ? feats[p * CIN + i] : 0.f;
    }
    __syncthreads();
    int pl = t >> 5, c = t & 31;
    int p = p0 + pl;
    float acc = u1b[c];
#pragma unroll
    for (int i = 0; i < CIN; i++) acc += sf[pl * CIN + i] * su[i * CMID + c];
    if (p < N) g_feats32[p * CMID + c] = acc;
}

// ============================================================================
// K2: 4 points per 128-thread block — r12-exact (baseline version)
// ============================================================================
__global__ __launch_bounds__(128) void k2_point(
    const float* __restrict__ xyz, const int* __restrict__ nei,
    const float* __restrict__ pw1, const float* __restrict__ pb1,
    const float* __restrict__ pw2, const float* __restrict__ pb2,
    const float* __restrict__ ww1, const float* __restrict__ wb1,
    const float* __restrict__ ww2, const float* __restrict__ wb2,
    const float* __restrict__ ww3, const float* __restrict__ wb3,
    float* __restrict__ loc_out, int N, int writeLoc)
{
    __shared__ float s_pw1[96], s_pb1[32];
    __shared__ __align__(16) float s_pw2[1024];
    __shared__ float s_pb2[32];
    __shared__ float s_ww1[24], s_wb1[8], s_ww2[64], s_wb2[8], s_ww3[128], s_wb3[16];
    __shared__ float s_loc[4][48];
    __shared__ __align__(16) float s_gf[4][512];
    __shared__ float s_ph[4][512];                  // [h][k] transposed
    __shared__ __align__(16) float s_pe[4][512];
    __shared__ float s_wh1[4][128], s_wh2[4][128];
    __shared__ __align__(16) float s_w[4][256];
    __shared__ int   s_nei[4][16];
    __shared__ float s_ctr[4][3];

    int p0 = blockIdx.x * 4;
    int t  = threadIdx.x;

    if (t < 96) s_pw1[t] = pw1[t];
    if (t < 32) { s_pb1[t] = pb1[t]; s_pb2[t] = pb2[t]; }
#pragma unroll
    for (int q = 0; q < 8; q++) s_pw2[q * 128 + t] = pw2[q * 128 + t];
    if (t < 24) s_ww1[t] = ww1[t];
    if (t >= 24 && t < 32) s_wb1[t - 24] = wb1[t - 24];
    if (t >= 32 && t < 96) s_ww2[t - 32] = ww2[t - 32];
    if (t >= 96 && t < 104) s_wb2[t - 96] = wb2[t - 96];
    s_ww3[t] = ww3[t];
    if (t >= 104 && t < 120) s_wb3[t - 104] = wb3[t - 104];
    if (t < 64) {
        int p = t >> 4, k = t & 15;
        s_nei[p][k] = (p0 + p < N) ? nei[(p0 + p) * KN + k] : 0;
    }
    if (t >= 64 && t < 76) {
        int i = t - 64, p = i / 3, d = i % 3;
        s_ctr[p][d] = (p0 + p < N) ? xyz[(p0 + p) * 3 + d] : 0.f;
    }
    __syncthreads();

#pragma unroll
    for (int q = 0; q < 2; q++) {
        int i = q * 128 + t;
        if (i < 192) {
            int p = i / 48, r = i - p * 48;
            int k = r / 3, d = r - k * 3;
            float v = xyz[s_nei[p][k] * 3 + d] - s_ctr[p][d];
            s_loc[p][r] = v;
            if (writeLoc && (p0 + p) < N) loc_out[(size_t)(p0 + p) * 48 + r] = v;
        }
    }
#pragma unroll
    for (int q = 0; q < 4; q++) {
        int idx = q * 128 + t;
        int p = idx >> 7, rem = idx & 127;
        int k = rem >> 3, c4 = (rem & 7) * 4;
        *(float4*)&s_gf[p][k * 32 + c4] =
            *(const float4*)&g_feats32[(size_t)s_nei[p][k] * CMID + c4];
    }
    __syncthreads();

    {
        int k = t & 15, hb = t >> 4;
#pragma unroll
        for (int p = 0; p < 4; p++) {
            float l0 = s_loc[p][k * 3], l1 = s_loc[p][k * 3 + 1], l2 = s_loc[p][k * 3 + 2];
#pragma unroll
            for (int q = 0; q < 4; q++) {
                int h = hb + q * 8;
                float a = s_pb1[h] + l0 * s_pw1[h] + l1 * s_pw1[32 + h] + l2 * s_pw1[64 + h];
                s_ph[p][h * 16 + k] = lrelu(a);
            }
        }
        int kk = t >> 3, hh = t & 7;
#pragma unroll
        for (int p = 0; p < 4; p++) {
            float m0 = s_loc[p][kk * 3], m1 = s_loc[p][kk * 3 + 1], m2 = s_loc[p][kk * 3 + 2];
            float a = s_wb1[hh] + m0 * s_ww1[hh] + m1 * s_ww1[8 + hh] + m2 * s_ww1[16 + hh];
            s_wh1[p][kk * 8 + hh] = lrelu(a);
        }
    }
    __syncthreads();

    {
        int k0 = t >> 4;
        int c0 = (t & 15) * 2;
        unsigned long long bias = pack2(s_pb2[c0], s_pb2[c0 + 1]);
        unsigned long long wreg[32];
#pragma unroll
        for (int h = 0; h < 32; h++)
            wreg[h] = *(const unsigned long long*)&s_pw2[h * 32 + c0];
#pragma unroll
        for (int q = 0; q < 2; q++) {
            int k = q * 8 + k0;
#pragma unroll
            for (int p = 0; p < 4; p++) {
                unsigned long long a = bias;
#pragma unroll
                for (int h = 0; h < 32; h++) {
                    float pv = s_ph[p][h * 16 + k];
                    unsigned long long ps = pack2(pv, pv);
                    FMA2(a, ps, wreg[h], a);
                }
                float x0, x1; unpack2(a, x0, x1);
                s_pe[p][k * 32 + c0]     = lrelu(x0);
                s_pe[p][k * 32 + c0 + 1] = lrelu(x1);
            }
        }
        int kk = t >> 3, hh = t & 7;
#pragma unroll
        for (int p = 0; p < 4; p++) {
            float a = s_wb2[hh];
#pragma unroll
            for (int j = 0; j < 8; j++) a += s_wh1[p][kk * 8 + j] * s_ww2[j * 8 + hh];
            s_wh2[p][kk * 8 + hh] = a;
        }
    }
    __syncthreads();

#pragma unroll
    for (int q = 0; q < 2; q++) {
        int idx = q * 128 + t;
        int k = idx >> 4, wo = idx & 15;
#pragma unroll
        for (int p = 0; p < 4; p++) {
            float a = s_wb3[wo];
#pragma unroll
            for (int j = 0; j < 8; j++) a += s_wh2[p][k * 8 + j] * s_ww3[j * 16 + wo];
            s_w[p][k * 16 + wo] = lrelu(a);
        }
    }
    __syncthreads();

#pragma unroll
    for (int q = 0; q < 2; q++) {
        int slot = q * 128 + t;
        int p = slot >> 6, c = slot & 63;
        const float* src = (c < 32) ? &s_gf[p][c] : &s_pe[p][c - 32];
        unsigned long long acc[8];
#pragma unroll
        for (int j = 0; j < 8; j++) acc[j] = 0ull;
#pragma unroll
        for (int k = 0; k < KN; k++) {
            float sv = src[k * 32];
            unsigned long long sp = pack2(sv, sv);
            ulonglong2 wa = *(const ulonglong2*)&s_w[p][k * 16];
            ulonglong2 wb = *(const ulonglong2*)&s_w[p][k * 16 + 4];
            ulonglong2 wc = *(const ulonglong2*)&s_w[p][k * 16 + 8];
            ulonglong2 wd = *(const ulonglong2*)&s_w[p][k * 16 + 12];
            FMA2(acc[0], sp, wa.x, acc[0]); FMA2(acc[1], sp, wa.y, acc[1]);
            FMA2(acc[2], sp, wb.x, acc[2]); FMA2(acc[3], sp, wb.y, acc[3]);
            FMA2(acc[4], sp, wc.x, acc[4]); FMA2(acc[5], sp, wc.y, acc[5]);
            FMA2(acc[6], sp, wd.x, acc[6]); FMA2(acc[7], sp, wd.y, acc[7]);
        }
        if (p0 + p < N) {
            float v[16];
#pragma unroll
            for (int j = 0; j < 8; j++) unpack2(acc[j], v[2 * j], v[2 * j + 1]);
            float* dst = &g_agg[(size_t)(p0 + p) * 1024 + c * 16];
            *(float4*)(dst)      = make_float4(v[0], v[1], v[2], v[3]);
            *(float4*)(dst + 4)  = make_float4(v[4], v[5], v[6], v[7]);
            *(float4*)(dst + 8)  = make_float4(v[8], v[9], v[10], v[11]);
            *(float4*)(dst + 12) = make_float4(v[12], v[13], v[14], v[15]);
        }
    }
}

// ============================================================================
// K3: warp-level bf16-split MMA — r15-exact (790.4us baseline version)
// ============================================================================
#define MST 40   // bf16 row stride
__global__ __launch_bounds__(256, 2) void k3_mma(
    const float* __restrict__ lw, const float* __restrict__ lb, int N)
{
    __shared__ __align__(16) unsigned short sAh[128 * MST];
    __shared__ __align__(16) unsigned short sAl[128 * MST];
    __shared__ __align__(16) unsigned short sBh[64 * MST];
    __shared__ __align__(16) unsigned short sBl[64 * MST];

    int t = threadIdx.x;
    int lane = t & 31, warp = t >> 5;
    int g = lane >> 2, tig = lane & 3;
    int mb = warp * 16;
    int tb = blockIdx.x * 128;

    float acc[8][4];
#pragma unroll
    for (int ns = 0; ns < 8; ns++)
#pragma unroll
        for (int i = 0; i < 4; i++) acc[ns][i] = 0.f;

    for (int ch = 0; ch < 32; ch++) {
        int kb = ch * 32;
#pragma unroll
        for (int q = 0; q < 4; q++) {
            int slot = q * 256 + t;
            int row = slot >> 3, seg = slot & 7;
            int grow = tb + row; if (grow >= N) grow = N - 1;
            float4 v = *(const float4*)&g_agg[(size_t)grow * 1024 + kb + seg * 4];
            unsigned hp0 = cvtbf2(v.x, v.y);
            unsigned hp1 = cvtbf2(v.z, v.w);
            float rx = v.x - __uint_as_float(hp0 << 16);
            float ry = v.y - __uint_as_float(hp0 & 0xFFFF0000u);
            float rz = v.z - __uint_as_float(hp1 << 16);
            float rw = v.w - __uint_as_float(hp1 & 0xFFFF0000u);
            unsigned lp0 = cvtbf2(rx, ry);
            unsigned lp1 = cvtbf2(rz, rw);
            uint2* dh = (uint2*)&sAh[row * MST + seg * 4];
            uint2* dl = (uint2*)&sAl[row * MST + seg * 4];
            *dh = make_uint2(hp0, hp1);
            *dl = make_uint2(lp0, lp1);
        }
#pragma unroll
        for (int q = 0; q < 2; q++) {
            int slot = q * 256 + t;
            int k = slot >> 4, n4 = (slot & 15) * 4;
            float4 v = *(const float4*)&lw[(size_t)(kb + k) * 64 + n4];
            float vv[4] = {v.x, v.y, v.z, v.w};
#pragma unroll
            for (int i = 0; i < 4; i++) {
                unsigned short h = f2bf(vv[i]);
                unsigned short l = f2bf(vv[i] - bf2f(h));
                sBh[(n4 + i) * MST + k] = h;
                sBl[(n4 + i) * MST + k] = l;
            }
        }
        __syncthreads();
#pragma unroll
        for (int ks = 0; ks < 2; ks++) {
            int ko = ks * 16 + tig * 2;
            unsigned ah[4], al[4];
            ah[0] = *(const unsigned*)&sAh[(mb + g) * MST + ko];
            ah[1] = *(const unsigned*)&sAh[(mb + g + 8) * MST + ko];
            ah[2] = *(const unsigned*)&sAh[(mb + g) * MST + ko + 8];
            ah[3] = *(const unsigned*)&sAh[(mb + g + 8) * MST + ko + 8];
            al[0] = *(const unsigned*)&sAl[(mb + g) * MST + ko];
            al[1] = *(const unsigned*)&sAl[(mb + g + 8) * MST + ko];
            al[2] = *(const unsigned*)&sAl[(mb + g) * MST + ko + 8];
            al[3] = *(const unsigned*)&sAl[(mb + g + 8) * MST + ko + 8];
#pragma unroll
            for (int ns = 0; ns < 8; ns++) {
                int n = ns * 8 + g;
                unsigned bh[2], bl[2];
                bh[0] = *(const unsigned*)&sBh[n * MST + ko];
                bh[1] = *(const unsigned*)&sBh[n * MST + ko + 8];
                bl[0] = *(const unsigned*)&sBl[n * MST + ko];
                bl[1] = *(const unsigned*)&sBl[n * MST + ko + 8];
                mma_bf16(acc[ns], ah, bh);
                mma_bf16(acc[ns], ah, bl);
                mma_bf16(acc[ns], al, bh);
            }
        }
        __syncthreads();
    }

    int ra = tb + mb + g;
    int rb = ra + 8;
#pragma unroll
    for (int ns = 0; ns < 8; ns++) {
        int c0 = ns * 8 + tig * 2;
        float b0 = lb[c0], b1 = lb[c0 + 1];
        if (ra < N) {
            float2* d = (float2*)&g_x[(size_t)ra * 64 + c0];
            *d = make_float2(lrelu(acc[ns][0] + b0), lrelu(acc[ns][1] + b1));
        }
        if (rb < N) {
            float2* d = (float2*)&g_x[(size_t)rb * 64 + c0];
            *d = make_float2(lrelu(acc[ns][2] + b0), lrelu(acc[ns][3] + b1));
        }
    }
}

// ============================================================================
// K4 (NEW): bf16-split MMA.  out = leaky([x|feats] @ [u2w;scw] + u2b+scb)
// 256 thr / 128 rows per CTA; warp = 16-row m-tile x N=128 (16 n-subtiles).
// K=128 in 4 chunks of 32 (chunks 0-1: g_x/u2w, 2-3: feats/scw).
// ============================================================================
__global__ __launch_bounds__(256) void k4_mma(
    const float* __restrict__ feats, const float* __restrict__ u2w,
    const float* __restrict__ u2b, const float* __restrict__ scw,
    const float* __restrict__ scb, float* __restrict__ out, int N)
{
    __shared__ __align__(16) unsigned short sAh[128 * MST];
    __shared__ __align__(16) unsigned short sAl[128 * MST];
    __shared__ __align__(16) unsigned short sBh[128 * MST];
    __shared__ __align__(16) unsigned short sBl[128 * MST];
    __shared__ float sb[128];

    int t = threadIdx.x;
    int lane = t & 31, warp = t >> 5;
    int g = lane >> 2, tig = lane & 3;
    int mb = warp * 16;
    int tb = blockIdx.x * 128;

    if (t < 128) sb[t] = u2b[t] + scb[t];

    float acc[16][4];
#pragma unroll
    for (int ns = 0; ns < 16; ns++)
#pragma unroll
        for (int i = 0; i < 4; i++) acc[ns][i] = 0.f;

    for (int ch = 0; ch < 4; ch++) {
        int kb = ch * 32;
        // ---- A: 128 rows x 32 k from g_x (kb<64) or feats ----
#pragma unroll
        for (int q = 0; q < 4; q++) {
            int slot = q * 256 + t;
            int row = slot >> 3, seg = slot & 7;
            int grow = tb + row; if (grow >= N) grow = N - 1;
            const float* src = (kb < 64)
                ? &g_x[(size_t)grow * 64 + kb + seg * 4]
                : &feats[(size_t)grow * 64 + (kb - 64) + seg * 4];
            float4 v = *(const float4*)src;
            unsigned hp0 = cvtbf2(v.x, v.y);
            unsigned hp1 = cvtbf2(v.z, v.w);
            float rx = v.x - __uint_as_float(hp0 << 16);
            float ry = v.y - __uint_as_float(hp0 & 0xFFFF0000u);
            float rz = v.z - __uint_as_float(hp1 << 16);
            float rw = v.w - __uint_as_float(hp1 & 0xFFFF0000u);
            unsigned lp0 = cvtbf2(rx, ry);
            unsigned lp1 = cvtbf2(rz, rw);
            *(uint2*)&sAh[row * MST + seg * 4] = make_uint2(hp0, hp1);
            *(uint2*)&sAl[row * MST + seg * 4] = make_uint2(lp0, lp1);
        }
        // ---- B: [u2w;scw] rows kb..kb+31 x 128 cols -> [n][k] ----
#pragma unroll
        for (int q = 0; q < 4; q++) {
            int slot = q * 256 + t;              // 1024 float4 slots
            int k = slot >> 5, n4 = (slot & 31) * 4;
            const float* w2 = (kb < 64)
                ? &u2w[(size_t)(kb + k) * 128 + n4]
                : &scw[(size_t)(kb - 64 + k) * 128 + n4];
            float4 v = *(const float4*)w2;
            float vv[4] = {v.x, v.y, v.z, v.w};
#pragma unroll
            for (int i = 0; i < 4; i++) {
                unsigned short h = f2bf(vv[i]);
                unsigned short l = f2bf(vv[i] - bf2f(h));
                sBh[(n4 + i) * MST + k] = h;
                sBl[(n4 + i) * MST + k] = l;
            }
        }
        __syncthreads();
#pragma unroll
        for (int ks = 0; ks < 2; ks++) {
            int ko = ks * 16 + tig * 2;
            unsigned ah[4], al[4];
            ah[0] = *(const unsigned*)&sAh[(mb + g) * MST + ko];
            ah[1] = *(const unsigned*)&sAh[(mb + g + 8) * MST + ko];
            ah[2] = *(const unsigned*)&sAh[(mb + g) * MST + ko + 8];
            ah[3] = *(const unsigned*)&sAh[(mb + g + 8) * MST + ko + 8];
            al[0] = *(const unsigned*)&sAl[(mb + g) * MST + ko];
            al[1] = *(const unsigned*)&sAl[(mb + g + 8) * MST + ko];
            al[2] = *(const unsigned*)&sAl[(mb + g) * MST + ko + 8];
            al[3] = *(const unsigned*)&sAl[(mb + g + 8) * MST + ko + 8];
#pragma unroll
            for (int ns = 0; ns < 16; ns++) {
                int n = ns * 8 + g;
                unsigned bh[2], bl[2];
                bh[0] = *(const unsigned*)&sBh[n * MST + ko];
                bh[1] = *(const unsigned*)&sBh[n * MST + ko + 8];
                bl[0] = *(const unsigned*)&sBl[n * MST + ko];
                bl[1] = *(const unsigned*)&sBl[n * MST + ko + 8];
                mma_bf16(acc[ns], ah, bh);
                mma_bf16(acc[ns], ah, bl);
                mma_bf16(acc[ns], al, bh);
            }
        }
        __syncthreads();
    }

    int ra = tb + mb + g;
    int rb = ra + 8;
#pragma unroll
    for (int ns = 0; ns < 16; ns++) {
        int c0 = ns * 8 + tig * 2;
        float b0 = sb[c0], b1 = sb[c0 + 1];
        if (ra < N) {
            float2* d = (float2*)&out[(size_t)ra * 128 + c0];
            *d = make_float2(lrelu(acc[ns][0] + b0), lrelu(acc[ns][1] + b1));
        }
        if (rb < N) {
            float2* d = (float2*)&out[(size_t)rb * 128 + c0];
            *d = make_float2(lrelu(acc[ns][2] + b0), lrelu(acc[ns][3] + b1));
        }
    }
}

// ============================================================================
// launch
// ============================================================================
extern "C" void kernel_launch(void* const* d_in, const int* in_sizes, int n_in,
                              void* d_out, int out_size)
{
    const float* xyz   = (const float*)d_in[0];
    const float* feats = (const float*)d_in[1];
    const int*   nei   = (const int*)  d_in[2];
    const float* pw1 = (const float*)d_in[3];
    const float* pb1 = (const float*)d_in[4];
    const float* pw2 = (const float*)d_in[5];
    const float* pb2 = (const float*)d_in[6];
    const float* u1w = (const float*)d_in[7];
    const float* u1b = (const float*)d_in[8];
    const float* ww1 = (const float*)d_in[9];
    const float* wb1 = (const float*)d_in[10];
    const float* ww2 = (const float*)d_in[11];
    const float* wb2 = (const float*)d_in[12];
    const float* ww3 = (const float*)d_in[13];
    const float* wb3 = (const float*)d_in[14];
    const float* lw  = (const float*)d_in[15];
    const float* lb  = (const float*)d_in[16];
    const float* u2w = (const float*)d_in[17];
    const float* u2b = (const float*)d_in[18];
    const float* scw = (const float*)d_in[19];
    const float* scb = (const float*)d_in[20];

    int N = in_sizes[0] / 3;
    if (N > NMAX) N = NMAX;

    float* out = (float*)d_out;
    long long need = (long long)N * 128 + (long long)N * 48;
    int writeLoc = ((long long)out_size >= need) ? 1 : 0;
    float* loc_out = out + (size_t)N * 128;

    k1_unary1<<<(N + 3) / 4, 128>>>(feats, u1w, u1b, N);
    k2_point<<<(N + 3) / 4, 128>>>(xyz, nei, pw1, pb1, pw2, pb2,
                                   ww1, wb1, ww2, wb2, ww3, wb3,
                                   loc_out, N, writeLoc);
    k3_mma<<<(N + 127) / 128, 256>>>(lw, lb, N);
    k4_mma<<<(N + 127) / 128, 256>>>(feats, u2w, u2b, scw, scb, out, N);
}